// round 2
// baseline (speedup 1.0000x reference)
#include <cuda_runtime.h>
#include <math.h>

// Problem constants (fixed by setup_inputs: B=64, N=1024, DEG=16, D=128)
#define D       128
#define BG      64
#define NPG0    1024
#define NN0     (BG * NPG0)        // 65536 nodes layer 1
#define EDGES   (BG * NPG0 * 16)   // 1048576 edges
#define K1      820                // ceil(0.8*1024)
#define K2      656                // ceil(0.8*820)
#define K3      525                // ceil(0.8*656)
#define N1      (BG * K1)          // 52480
#define N2      (BG * K2)          // 41984
#define N3      (BG * K3)          // 33600

// ---------------- scratch (device globals; no allocation allowed) -----------
__device__ float          g_agg[NN0 * D];     // 32MB
__device__ float          g_cnt[NN0];
__device__ float          g_h[NN0 * D];       // 32MB  (SAGE+ReLU output)
__device__ float          g_xa[N1 * D];       // pooled features buffer A
__device__ float          g_xb[N2 * D];       // pooled features buffer B
__device__ float          g_score[NN0];
__device__ int            g_newid[NN0];
__device__ int            g_oldof[N1];
__device__ float          g_vals[N1];
__device__ int            g_src[EDGES];
__device__ int            g_dst[EDGES];
__device__ unsigned char  g_mask[EDGES];
__device__ float          g_s[BG * 256];      // readout accumulator
__device__ float          g_invnorm;

// Select which feature buffer a kernel reads/writes (avoid host symbol lookups)
__device__ __forceinline__ const float* sel_in(const float* ext, int sel) {
    return (sel == 1) ? g_xa : (sel == 2) ? g_xb : ext;
}
__device__ __forceinline__ float* sel_out(int sel) {
    return (sel == 1) ? g_xa : g_xb;
}

// ---------------- init: copy edges, set mask=1, zero readout accumulator ----
__global__ void init_kernel(const int* __restrict__ ei) {
    int i = blockIdx.x * blockDim.x + threadIdx.x;
    if (i < EDGES) {
        g_src[i] = ei[i];
        g_dst[i] = ei[EDGES + i];
        g_mask[i] = 1;
    }
    if (i < BG * 256) g_s[i] = 0.0f;
}

// ---------------- zero agg + cnt for current layer --------------------------
__global__ void zero_kernel(int n) {
    int i = blockIdx.x * blockDim.x + threadIdx.x;
    if (i < n * D) g_agg[i] = 0.0f;
    if (i < n)     g_cnt[i] = 0.0f;
}

// ---------------- edge scatter: agg[dst] += x[src]; cnt[dst] += 1 -----------
// 32 lanes per edge, float4 per lane, vector RED to global.
__global__ void scatter_kernel(const float* __restrict__ x_ext, int xsel) {
    int gid  = blockIdx.x * blockDim.x + threadIdx.x;
    int e    = gid >> 5;
    if (e >= EDGES) return;
    if (!g_mask[e]) return;
    const float* x = sel_in(x_ext, xsel);
    int lane = gid & 31;
    int s = g_src[e], d = g_dst[e];
    float4 v = ((const float4*)(x + (size_t)s * D))[lane];
    float* ap = g_agg + (size_t)d * D + lane * 4;
    asm volatile("red.global.add.v4.f32 [%0], {%1,%2,%3,%4};"
                 :: "l"(ap), "f"(v.x), "f"(v.y), "f"(v.z), "f"(v.w) : "memory");
    if (lane == 0) atomicAdd(&g_cnt[d], 1.0f);
}

// ---------------- h = relu(mean @ Wl + bl + x @ Wr) -------------------------
// 32 rows per block, 64 threads, 2 output cols per thread.
__global__ __launch_bounds__(64) void sage_gemm_kernel(
    const float* __restrict__ x_ext, int xsel,
    const float* __restrict__ Wl, const float* __restrict__ bl,
    const float* __restrict__ Wr)
{
    __shared__ float sM[32 * D];
    __shared__ float sX[32 * D];
    const float* x = sel_in(x_ext, xsel);
    int tid  = threadIdx.x;
    int row0 = blockIdx.x * 32;

    for (int i = tid; i < 32 * D; i += 64) {
        int r = i >> 7;
        float c   = g_cnt[row0 + r];
        float inv = 1.0f / fmaxf(c, 1.0f);
        sM[i] = g_agg[(size_t)row0 * D + i] * inv;
        sX[i] = x[(size_t)row0 * D + i];
    }
    __syncthreads();

    int j0 = tid, j1 = tid + 64;
    float acc0[32], acc1[32];
#pragma unroll
    for (int r = 0; r < 32; r++) { acc0[r] = 0.0f; acc1[r] = 0.0f; }

#pragma unroll 4
    for (int k = 0; k < D; k++) {
        float wl0 = Wl[k * D + j0], wl1 = Wl[k * D + j1];
        float wr0 = Wr[k * D + j0], wr1 = Wr[k * D + j1];
#pragma unroll
        for (int r = 0; r < 32; r++) {
            float m = sM[r * D + k], xx = sX[r * D + k];
            acc0[r] += m * wl0 + xx * wr0;
            acc1[r] += m * wl1 + xx * wr1;
        }
    }
    float b0 = bl[j0], b1 = bl[j1];
#pragma unroll
    for (int r = 0; r < 32; r++) {
        g_h[(size_t)(row0 + r) * D + j0] = fmaxf(acc0[r] + b0, 0.0f);
        g_h[(size_t)(row0 + r) * D + j1] = fmaxf(acc1[r] + b1, 0.0f);
    }
}

// ---------------- 1/||pw|| --------------------------------------------------
__global__ void invnorm_kernel(const float* __restrict__ pw) {
    __shared__ float red[128];
    float v = pw[threadIdx.x];
    red[threadIdx.x] = v * v;
    __syncthreads();
    for (int s = 64; s > 0; s >>= 1) {
        if (threadIdx.x < s) red[threadIdx.x] += red[threadIdx.x + s];
        __syncthreads();
    }
    if (threadIdx.x == 0) g_invnorm = rsqrtf(red[0]);
}

// ---------------- score = tanh((h . pw) * invnorm), warp per node -----------
__global__ void score_kernel(const float* __restrict__ pw, int n) {
    int warp = (blockIdx.x * blockDim.x + threadIdx.x) >> 5;
    int lane = threadIdx.x & 31;
    if (warp >= n) return;
    float4 h4 = ((const float4*)(g_h + (size_t)warp * D))[lane];
    float4 w4 = ((const float4*)pw)[lane];
    float dot = h4.x * w4.x + h4.y * w4.y + h4.z * w4.z + h4.w * w4.w;
#pragma unroll
    for (int o = 16; o > 0; o >>= 1) dot += __shfl_down_sync(0xffffffffu, dot, o);
    if (lane == 0) g_score[warp] = tanhf(dot * g_invnorm);
}

// ---------------- per-graph top-K via bitonic sort (P=1024) -----------------
__global__ void topk_kernel(int Npg, int K) {
    __shared__ float ss[1024];
    __shared__ int   si[1024];
    int g = blockIdx.x, t = threadIdx.x;
    if (t < Npg) { ss[t] = g_score[g * Npg + t]; si[t] = t; }
    else         { ss[t] = -1e30f;               si[t] = -1; }
    __syncthreads();

    for (int k = 2; k <= 1024; k <<= 1) {
        for (int j = k >> 1; j > 0; j >>= 1) {
            int ixj = t ^ j;
            if (ixj > t) {
                bool desc = ((t & k) == 0);
                float a = ss[t], b = ss[ixj];
                bool sw = desc ? (a < b) : (a > b);
                if (sw) {
                    ss[t] = b; ss[ixj] = a;
                    int tmp = si[t]; si[t] = si[ixj]; si[ixj] = tmp;
                }
            }
            __syncthreads();
        }
    }
    if (t < Npg) {
        int oldg = g * Npg + si[t];
        if (t < K) {
            int nw = g * K + t;
            g_newid[oldg] = nw;
            g_oldof[nw]   = oldg;
            g_vals[nw]    = ss[t];
        } else {
            g_newid[oldg] = -1;
        }
    }
}

// ---------------- x_new[nw] = h[old] * score --------------------------------
__global__ void gather_kernel(int outsel) {
    float* xout = sel_out(outsel);
    int nw = blockIdx.x, t = threadIdx.x;   // 32 threads
    int old = g_oldof[nw];
    float v  = g_vals[nw];
    float4 h4 = ((const float4*)(g_h + (size_t)old * D))[t];
    float4 o = make_float4(h4.x * v, h4.y * v, h4.z * v, h4.w * v);
    ((float4*)(xout + (size_t)nw * D))[t] = o;
}

// ---------------- readout: s[g] += [max || mean] over K nodes ---------------
__global__ void readout_kernel(int insel, int K) {
    __shared__ float smax[4][128];
    __shared__ float ssum[4][128];
    const float* xn = sel_in(nullptr, insel);
    int g = blockIdx.x, t = threadIdx.x;
    int c = t >> 7, f = t & 127;
    float mx = -1e30f, sm = 0.0f;
    for (int k = c; k < K; k += 4) {
        float v = xn[((size_t)(g * K + k)) * D + f];
        mx = fmaxf(mx, v);
        sm += v;
    }
    smax[c][f] = mx; ssum[c][f] = sm;
    __syncthreads();
    if (c == 0) {
#pragma unroll
        for (int i = 1; i < 4; i++) { mx = fmaxf(mx, smax[i][f]); sm += ssum[i][f]; }
        g_s[g * 256 + f]       += mx;
        g_s[g * 256 + 128 + f] += sm / (float)K;
    }
}

// ---------------- remap edges through new_id, update mask -------------------
__global__ void remap_kernel() {
    int e = blockIdx.x * blockDim.x + threadIdx.x;
    if (e >= EDGES) return;
    if (!g_mask[e]) return;
    int s = g_newid[g_src[e]];
    int d = g_newid[g_dst[e]];
    if (s < 0 || d < 0) { g_mask[e] = 0; g_src[e] = 0; g_dst[e] = 0; }
    else                { g_src[e] = s; g_dst[e] = d; }
}

// ---------------- final MLP head: 256->128->64->1, sigmoid ------------------
__global__ void mlp_kernel(const float* __restrict__ W1, const float* __restrict__ b1,
                           const float* __restrict__ W2, const float* __restrict__ b2,
                           const float* __restrict__ W3, const float* __restrict__ b3,
                           float* __restrict__ out)
{
    __shared__ float ss[256];
    __shared__ float h1[128];
    __shared__ float h2[64];
    int g = blockIdx.x, t = threadIdx.x;   // 128 threads
    ss[t]       = g_s[g * 256 + t];
    ss[t + 128] = g_s[g * 256 + 128 + t];
    __syncthreads();
    float a = b1[t];
    for (int k = 0; k < 256; k++) a += ss[k] * W1[k * 128 + t];
    h1[t] = fmaxf(a, 0.0f);
    __syncthreads();
    if (t < 64) {
        float a2 = b2[t];
        for (int k = 0; k < 128; k++) a2 += h1[k] * W2[k * 64 + t];
        h2[t] = fmaxf(a2, 0.0f);
    }
    __syncthreads();
    if (t == 0) {
        float s2 = 0.0f;
        for (int i = 0; i < 64; i++) s2 += h2[i] * W3[i];
        out[g] = 1.0f / (1.0f + expf(-(s2 + b3[0])));
    }
}

// ---------------- host orchestration ----------------------------------------
static void run_layer(const float* x_ext, int xsel, int n, int Npg, int K,
                      const float* Wl, const float* bl, const float* Wr,
                      const float* pw, int outsel, bool remap)
{
    zero_kernel<<<(n * D + 255) / 256, 256>>>(n);
    scatter_kernel<<<(EDGES * 32) / 256, 256>>>(x_ext, xsel);
    sage_gemm_kernel<<<n / 32, 64>>>(x_ext, xsel, Wl, bl, Wr);
    invnorm_kernel<<<1, 128>>>(pw);
    score_kernel<<<n / 8, 256>>>(pw, n);
    topk_kernel<<<BG, 1024>>>(Npg, K);
    gather_kernel<<<BG * K, 32>>>(outsel);
    readout_kernel<<<BG, 512>>>(outsel, K);
    if (remap) remap_kernel<<<(EDGES + 255) / 256, 256>>>();
}

extern "C" void kernel_launch(void* const* d_in, const int* in_sizes, int n_in,
                              void* d_out, int out_size)
{
    const float* x   = (const float*)d_in[0];
    const int*   ei  = (const int*)  d_in[1];
    const float* Wl1 = (const float*)d_in[2];
    const float* bl1 = (const float*)d_in[3];
    const float* Wr1 = (const float*)d_in[4];
    const float* pw1 = (const float*)d_in[5];
    const float* Wl2 = (const float*)d_in[6];
    const float* bl2 = (const float*)d_in[7];
    const float* Wr2 = (const float*)d_in[8];
    const float* pw2 = (const float*)d_in[9];
    const float* Wl3 = (const float*)d_in[10];
    const float* bl3 = (const float*)d_in[11];
    const float* Wr3 = (const float*)d_in[12];
    const float* pw3 = (const float*)d_in[13];
    const float* W1  = (const float*)d_in[14];
    const float* b1  = (const float*)d_in[15];
    const float* W2  = (const float*)d_in[16];
    const float* b2  = (const float*)d_in[17];
    const float* W3  = (const float*)d_in[18];
    const float* b3  = (const float*)d_in[19];

    init_kernel<<<EDGES / 256, 256>>>(ei);
    // layer 1: input x (external), pooled output -> g_xa (sel 1)
    run_layer(x,       0, NN0, NPG0, K1, Wl1, bl1, Wr1, pw1, 1, true);
    // layer 2: input g_xa, pooled output -> g_xb (sel 2)
    run_layer(nullptr, 1, N1,  K1,   K2, Wl2, bl2, Wr2, pw2, 2, true);
    // layer 3: input g_xb, pooled output -> g_xa (reuse; N3 < N1). No remap.
    run_layer(nullptr, 2, N2,  K2,   K3, Wl3, bl3, Wr3, pw3, 1, false);

    mlp_kernel<<<BG, 128>>>(W1, b1, W2, b2, W3, b3, (float*)d_out);
}

// round 7
// speedup vs baseline: 1.4632x; 1.4632x over previous
#include <cuda_runtime.h>
#include <cstdint>
#include <math.h>

// Problem constants (fixed by setup_inputs: B=64, N=1024, DEG=16, D=128)
#define D       128
#define BG      64
#define NPG0    1024
#define NN0     (BG * NPG0)        // 65536 nodes layer 1
#define EDGES   (BG * NPG0 * 16)   // 1048576 edges
#define K1      820
#define K2      656
#define K3      525
#define N1      (BG * K1)          // 52480
#define N2      (BG * K2)          // 41984
#define N3      (BG * K3)          // 33600

// ---------------- scratch (device globals; no allocation allowed) -----------
__device__ float          g_agg[NN0 * D];
__device__ float          g_cnt[NN0];
__device__ float          g_h[NN0 * D];
__device__ float          g_xa[N1 * D];
__device__ float          g_xb[N2 * D];
__device__ float          g_score[NN0];
__device__ int            g_newid[NN0];
__device__ int            g_oldof[N1];
__device__ float          g_vals[N1];
__device__ int            g_src[EDGES];
__device__ int            g_dst[EDGES];
__device__ unsigned char  g_mask[EDGES];
__device__ float          g_s[BG * 256];
__device__ float          g_invnorm3[3];

__device__ __forceinline__ const float* sel_in(const float* ext, int sel) {
    return (sel == 1) ? g_xa : (sel == 2) ? g_xb : ext;
}
__device__ __forceinline__ float* sel_out(int sel) {
    return (sel == 1) ? g_xa : g_xb;
}

// ===================== tf32 mma helpers (sm_80+, no 'a' features) ===========
__device__ __forceinline__ void mma_tf32(float* d,
    uint32_t a0, uint32_t a1, uint32_t a2, uint32_t a3,
    uint32_t b0, uint32_t b1)
{
    asm volatile(
        "mma.sync.aligned.m16n8k8.row.col.f32.tf32.tf32.f32 "
        "{%0,%1,%2,%3}, {%4,%5,%6,%7}, {%8,%9}, {%0,%1,%2,%3};"
        : "+f"(d[0]), "+f"(d[1]), "+f"(d[2]), "+f"(d[3])
        : "r"(a0), "r"(a1), "r"(a2), "r"(a3), "r"(b0), "r"(b1));
}

// Split fp32 into tf32 hi + tf32(residual) lo for tf32x3 fp32 emulation.
__device__ __forceinline__ void f32_to_tf32x2(float v, uint32_t& hi, uint32_t& lo) {
    asm("cvt.rna.tf32.f32 %0, %1;" : "=r"(hi) : "f"(v));
    float r = v - __uint_as_float(hi);
    asm("cvt.rna.tf32.f32 %0, %1;" : "=r"(lo) : "f"(r));
}

// ===================== init / zero / scatter ================================
__global__ void init_kernel(const int* __restrict__ ei) {
    int i = blockIdx.x * blockDim.x + threadIdx.x;
    if (i < EDGES) {
        g_src[i] = ei[i];
        g_dst[i] = ei[EDGES + i];
        g_mask[i] = 1;
    }
    if (i < BG * 256) g_s[i] = 0.0f;
}

__global__ void zero_kernel(int n) {
    int i = blockIdx.x * blockDim.x + threadIdx.x;
    if (i < n * D) g_agg[i] = 0.0f;
    if (i < n)     g_cnt[i] = 0.0f;
}

__global__ void scatter_kernel(const float* __restrict__ x_ext, int xsel) {
    int gid  = blockIdx.x * blockDim.x + threadIdx.x;
    int e    = gid >> 5;
    if (e >= EDGES) return;
    if (!g_mask[e]) return;
    const float* x = sel_in(x_ext, xsel);
    int lane = gid & 31;
    int s = g_src[e], d = g_dst[e];
    float4 v = ((const float4*)(x + (size_t)s * D))[lane];
    float* ap = g_agg + (size_t)d * D + lane * 4;
    asm volatile("red.global.add.v4.f32 [%0], {%1,%2,%3,%4};"
                 :: "l"(ap), "f"(v.x), "f"(v.y), "f"(v.z), "f"(v.w) : "memory");
    if (lane == 0) atomicAdd(&g_cnt[d], 1.0f);
}

// ===================== invnorm for all 3 pool weights =======================
__global__ void invnorm_kernel(const float* __restrict__ pw1,
                               const float* __restrict__ pw2,
                               const float* __restrict__ pw3) {
    const float* pw = (blockIdx.x == 0) ? pw1 : (blockIdx.x == 1) ? pw2 : pw3;
    __shared__ float red[128];
    float v = pw[threadIdx.x];
    red[threadIdx.x] = v * v;
    __syncthreads();
    for (int s = 64; s > 0; s >>= 1) {
        if (threadIdx.x < s) red[threadIdx.x] += red[threadIdx.x + s];
        __syncthreads();
    }
    if (threadIdx.x == 0) g_invnorm3[blockIdx.x] = rsqrtf(red[0]);
}

// ===================== fused SAGE GEMM (mma.sync tf32x3) + score ============
// h[128 x 128] = relu([mean | x](128x256) @ [Wl;Wr](256x128) + bl)
// score = tanh(dot(h,pw)*invnorm)  — fused epilogue.
// 256 threads = 8 warps (4 x 2), warp tile 32x64, K staged 16 at a time.
#define AS_STRIDE 20     // 128 rows x (16 + pad) floats — conflict-free frag LDS
#define BS_STRIDE 136    // 16 k-rows x (128 + pad)      — conflict-free frag LDS

__device__ __forceinline__ void sage_gload(float4* ra, float4* rb, int s,
    int row0, int n, const float* __restrict__ x,
    const float* __restrict__ Wl, const float* __restrict__ Wr,
    const float* sInv, int tid)
{
    int k0 = s * 16;
#pragma unroll
    for (int p = 0; p < 2; p++) {
        int idx = tid + p * 256;
        int r = idx >> 2, c4 = (idx & 3) << 2;
        int node = row0 + r; if (node >= n) node = n - 1;
        float4 v;
        if (k0 < 128) {
            v = *(const float4*)(g_agg + (size_t)node * D + k0 + c4);
            float iv = sInv[r];
            v.x *= iv; v.y *= iv; v.z *= iv; v.w *= iv;
        } else {
            v = *(const float4*)(x + (size_t)node * D + (k0 - 128) + c4);
        }
        ra[p] = v;
        int k = idx >> 5, n4 = (idx & 31) << 2;
        int kg = k0 + k;
        const float* Ws = (kg < 128) ? (Wl + (size_t)kg * D + n4)
                                     : (Wr + (size_t)(kg - 128) * D + n4);
        rb[p] = *(const float4*)Ws;
    }
}

__device__ __forceinline__ void sage_sstore(const float4* ra, const float4* rb,
    float* Ab, float* Bb, int tid)
{
#pragma unroll
    for (int p = 0; p < 2; p++) {
        int idx = tid + p * 256;
        int r = idx >> 2, c4 = (idx & 3) << 2;
        *(float4*)(Ab + r * AS_STRIDE + c4) = ra[p];
        int k = idx >> 5, n4 = (idx & 31) << 2;
        *(float4*)(Bb + k * BS_STRIDE + n4) = rb[p];
    }
}

__device__ __forceinline__ void sage_compute(float acc[2][8][4],
    const float* Ab, const float* Bb, int wm, int wn, int l4, int lq)
{
#pragma unroll
    for (int q = 0; q < 2; q++) {
        int kb = q * 8;
        uint32_t ah[2][4], al[2][4];
#pragma unroll
        for (int i = 0; i < 2; i++) {
            int rbase = wm * 32 + i * 16 + l4;
#pragma unroll
            for (int e = 0; e < 4; e++) {
                int rr = rbase + (e & 1) * 8;
                int kk = kb + lq + (e >> 1) * 4;
                f32_to_tf32x2(Ab[rr * AS_STRIDE + kk], ah[i][e], al[i][e]);
            }
        }
#pragma unroll
        for (int j = 0; j < 8; j++) {
            int nb = wn * 64 + j * 8 + l4;
            uint32_t bh0, blo0, bh1, blo1;
            f32_to_tf32x2(Bb[(kb + lq) * BS_STRIDE + nb], bh0, blo0);
            f32_to_tf32x2(Bb[(kb + lq + 4) * BS_STRIDE + nb], bh1, blo1);
#pragma unroll
            for (int i = 0; i < 2; i++) {
                mma_tf32(acc[i][j], ah[i][0], ah[i][1], ah[i][2], ah[i][3], bh0, bh1);
                mma_tf32(acc[i][j], ah[i][0], ah[i][1], ah[i][2], ah[i][3], blo0, blo1);
                mma_tf32(acc[i][j], al[i][0], al[i][1], al[i][2], al[i][3], bh0, bh1);
            }
        }
    }
}

__global__ __launch_bounds__(256) void sage_mma_kernel(
    const float* __restrict__ x_ext, int xsel,
    const float* __restrict__ Wl, const float* __restrict__ bl,
    const float* __restrict__ Wr, const float* __restrict__ pw,
    int layer, int n)
{
    __shared__ float As[2][128 * AS_STRIDE];
    __shared__ float Bs[2][16 * BS_STRIDE];
    __shared__ float sInv[128], sBias[128], sPw[128];
    __shared__ float sDot[128][2];

    const float* x = sel_in(x_ext, xsel);
    int tid = threadIdx.x;
    int wid = tid >> 5, lane = tid & 31;
    int wm = wid & 3, wn = wid >> 2;
    int l4 = lane >> 2, lq = lane & 3;
    int row0 = blockIdx.x * 128;

    if (tid < 128) {
        int node = row0 + tid; if (node >= n) node = n - 1;
        sInv[tid]  = 1.0f / fmaxf(g_cnt[node], 1.0f);
        sBias[tid] = bl[tid];
        sPw[tid]   = pw[tid];
    }
    __syncthreads();

    float acc[2][8][4];
#pragma unroll
    for (int i = 0; i < 2; i++)
#pragma unroll
        for (int j = 0; j < 8; j++)
#pragma unroll
            for (int e = 0; e < 4; e++) acc[i][j][e] = 0.0f;

    float4 ra[2], rb[2];
    sage_gload(ra, rb, 0, row0, n, x, Wl, Wr, sInv, tid);
    sage_sstore(ra, rb, As[0], Bs[0], tid);
    __syncthreads();

#pragma unroll 1
    for (int s = 0; s < 16; s++) {
        if (s < 15) sage_gload(ra, rb, s + 1, row0, n, x, Wl, Wr, sInv, tid);
        sage_compute(acc, As[s & 1], Bs[s & 1], wm, wn, l4, lq);
        if (s < 15) {
            sage_sstore(ra, rb, As[(s + 1) & 1], Bs[(s + 1) & 1], tid);
            __syncthreads();
        }
    }

    // ---- epilogue: bias + relu + store h + fused pool-score dot ----
    float dA[2] = {0.0f, 0.0f}, dB[2] = {0.0f, 0.0f};
#pragma unroll
    for (int i = 0; i < 2; i++) {
        int rA = wm * 32 + i * 16 + l4;
        int nodeA = row0 + rA, nodeB = nodeA + 8;
#pragma unroll
        for (int j = 0; j < 8; j++) {
            int c0 = wn * 64 + j * 8 + 2 * lq;
            float o0 = fmaxf(acc[i][j][0] + sBias[c0],     0.0f);
            float o1 = fmaxf(acc[i][j][1] + sBias[c0 + 1], 0.0f);
            float o2 = fmaxf(acc[i][j][2] + sBias[c0],     0.0f);
            float o3 = fmaxf(acc[i][j][3] + sBias[c0 + 1], 0.0f);
            if (nodeA < n) *(float2*)(g_h + (size_t)nodeA * D + c0) = make_float2(o0, o1);
            if (nodeB < n) *(float2*)(g_h + (size_t)nodeB * D + c0) = make_float2(o2, o3);
            dA[i] += o0 * sPw[c0] + o1 * sPw[c0 + 1];
            dB[i] += o2 * sPw[c0] + o3 * sPw[c0 + 1];
        }
    }
#pragma unroll
    for (int o = 1; o <= 2; o <<= 1) {
        dA[0] += __shfl_xor_sync(0xffffffffu, dA[0], o);
        dA[1] += __shfl_xor_sync(0xffffffffu, dA[1], o);
        dB[0] += __shfl_xor_sync(0xffffffffu, dB[0], o);
        dB[1] += __shfl_xor_sync(0xffffffffu, dB[1], o);
    }
    if (lq == 0) {
        sDot[wm * 32 + l4][wn]      = dA[0];
        sDot[wm * 32 + l4 + 8][wn]  = dB[0];
        sDot[wm * 32 + l4 + 16][wn] = dA[1];
        sDot[wm * 32 + l4 + 24][wn] = dB[1];
    }
    __syncthreads();
    if (tid < 128 && row0 + tid < n) {
        float dsum = sDot[tid][0] + sDot[tid][1];
        g_score[row0 + tid] = tanhf(dsum * g_invnorm3[layer]);
    }
}

// ===================== topk / gather / readout / remap / mlp ================
__global__ void topk_kernel(int Npg, int K) {
    __shared__ float ss[1024];
    __shared__ int   si[1024];
    int g = blockIdx.x, t = threadIdx.x;
    if (t < Npg) { ss[t] = g_score[g * Npg + t]; si[t] = t; }
    else         { ss[t] = -1e30f;               si[t] = -1; }
    __syncthreads();
    for (int k = 2; k <= 1024; k <<= 1) {
        for (int j = k >> 1; j > 0; j >>= 1) {
            int ixj = t ^ j;
            if (ixj > t) {
                bool desc = ((t & k) == 0);
                float a = ss[t], b = ss[ixj];
                bool sw = desc ? (a < b) : (a > b);
                if (sw) {
                    ss[t] = b; ss[ixj] = a;
                    int tmp = si[t]; si[t] = si[ixj]; si[ixj] = tmp;
                }
            }
            __syncthreads();
        }
    }
    if (t < Npg) {
        int oldg = g * Npg + si[t];
        if (t < K) {
            int nw = g * K + t;
            g_newid[oldg] = nw;
            g_oldof[nw]   = oldg;
            g_vals[nw]    = ss[t];
        } else {
            g_newid[oldg] = -1;
        }
    }
}

__global__ void gather_kernel(int outsel) {
    float* xout = sel_out(outsel);
    int nw = blockIdx.x, t = threadIdx.x;   // 32 threads
    int old = g_oldof[nw];
    float v  = g_vals[nw];
    float4 h4 = ((const float4*)(g_h + (size_t)old * D))[t];
    float4 o = make_float4(h4.x * v, h4.y * v, h4.z * v, h4.w * v);
    ((float4*)(xout + (size_t)nw * D))[t] = o;
}

__global__ void readout_kernel(int insel, int K) {
    __shared__ float smax[4][128];
    __shared__ float ssum[4][128];
    const float* xn = sel_in(nullptr, insel);
    int g = blockIdx.x, t = threadIdx.x;
    int c = t >> 7, f = t & 127;
    float mx = -1e30f, sm = 0.0f;
    for (int k = c; k < K; k += 4) {
        float v = xn[((size_t)(g * K + k)) * D + f];
        mx = fmaxf(mx, v);
        sm += v;
    }
    smax[c][f] = mx; ssum[c][f] = sm;
    __syncthreads();
    if (c == 0) {
#pragma unroll
        for (int i = 1; i < 4; i++) { mx = fmaxf(mx, smax[i][f]); sm += ssum[i][f]; }
        g_s[g * 256 + f]       += mx;
        g_s[g * 256 + 128 + f] += sm / (float)K;
    }
}

__global__ void remap_kernel() {
    int e = blockIdx.x * blockDim.x + threadIdx.x;
    if (e >= EDGES) return;
    if (!g_mask[e]) return;
    int s = g_newid[g_src[e]];
    int d = g_newid[g_dst[e]];
    if (s < 0 || d < 0) { g_mask[e] = 0; g_src[e] = 0; g_dst[e] = 0; }
    else                { g_src[e] = s; g_dst[e] = d; }
}

__global__ void mlp_kernel(const float* __restrict__ W1, const float* __restrict__ b1,
                           const float* __restrict__ W2, const float* __restrict__ b2,
                           const float* __restrict__ W3, const float* __restrict__ b3,
                           float* __restrict__ out)
{
    __shared__ float ss[256];
    __shared__ float h1[128];
    __shared__ float h2[64];
    int g = blockIdx.x, t = threadIdx.x;   // 128 threads
    ss[t]       = g_s[g * 256 + t];
    ss[t + 128] = g_s[g * 256 + 128 + t];
    __syncthreads();
    float a = b1[t];
    for (int k = 0; k < 256; k++) a += ss[k] * W1[k * 128 + t];
    h1[t] = fmaxf(a, 0.0f);
    __syncthreads();
    if (t < 64) {
        float a2 = b2[t];
        for (int k = 0; k < 128; k++) a2 += h1[k] * W2[k * 64 + t];
        h2[t] = fmaxf(a2, 0.0f);
    }
    __syncthreads();
    if (t == 0) {
        float s2 = 0.0f;
        for (int i = 0; i < 64; i++) s2 += h2[i] * W3[i];
        out[g] = 1.0f / (1.0f + expf(-(s2 + b3[0])));
    }
}

// ===================== host orchestration ===================================
static void run_layer(const float* x_ext, int xsel, int n, int Npg, int K,
                      const float* Wl, const float* bl, const float* Wr,
                      const float* pw, int layer, int outsel, bool remap)
{
    zero_kernel<<<(n * D + 255) / 256, 256>>>(n);
    scatter_kernel<<<(EDGES * 32) / 256, 256>>>(x_ext, xsel);
    sage_mma_kernel<<<(n + 127) / 128, 256>>>(x_ext, xsel, Wl, bl, Wr, pw, layer, n);
    topk_kernel<<<BG, 1024>>>(Npg, K);
    gather_kernel<<<BG * K, 32>>>(outsel);
    readout_kernel<<<BG, 512>>>(outsel, K);
    if (remap) remap_kernel<<<(EDGES + 255) / 256, 256>>>();
}

extern "C" void kernel_launch(void* const* d_in, const int* in_sizes, int n_in,
                              void* d_out, int out_size)
{
    const float* x   = (const float*)d_in[0];
    const int*   ei  = (const int*)  d_in[1];
    const float* Wl1 = (const float*)d_in[2];
    const float* bl1 = (const float*)d_in[3];
    const float* Wr1 = (const float*)d_in[4];
    const float* pw1 = (const float*)d_in[5];
    const float* Wl2 = (const float*)d_in[6];
    const float* bl2 = (const float*)d_in[7];
    const float* Wr2 = (const float*)d_in[8];
    const float* pw2 = (const float*)d_in[9];
    const float* Wl3 = (const float*)d_in[10];
    const float* bl3 = (const float*)d_in[11];
    const float* Wr3 = (const float*)d_in[12];
    const float* pw3 = (const float*)d_in[13];
    const float* W1  = (const float*)d_in[14];
    const float* b1  = (const float*)d_in[15];
    const float* W2  = (const float*)d_in[16];
    const float* b2  = (const float*)d_in[17];
    const float* W3  = (const float*)d_in[18];
    const float* b3  = (const float*)d_in[19];

    init_kernel<<<EDGES / 256, 256>>>(ei);
    invnorm_kernel<<<3, 128>>>(pw1, pw2, pw3);

    run_layer(x,       0, NN0, NPG0, K1, Wl1, bl1, Wr1, pw1, 0, 1, true);
    run_layer(nullptr, 1, N1,  K1,   K2, Wl2, bl2, Wr2, pw2, 1, 2, true);
    run_layer(nullptr, 2, N2,  K2,   K3, Wl3, bl3, Wr3, pw3, 2, 1, false);

    mlp_kernel<<<BG, 128>>>(W1, b1, W2, b2, W3, b3, (float*)d_out);
}

// round 8
// speedup vs baseline: 2.1628x; 1.4781x over previous
#include <cuda_runtime.h>
#include <cstdint>
#include <math.h>

// Problem constants (fixed by setup_inputs: B=64, N=1024, DEG=16, D=128)
#define D       128
#define BG      64
#define NPG0    1024
#define NN0     (BG * NPG0)        // 65536 nodes layer 1
#define EDGES   (BG * NPG0 * 16)   // 1048576 edges
#define EPG     16384              // CSR capacity per graph
#define K1      820
#define K2      656
#define K3      525
#define N1      (BG * K1)          // 52480
#define N2      (BG * K2)          // 41984
#define N3      (BG * K3)          // 33600

// ---------------- scratch (device globals; no allocation allowed) -----------
__device__ float          g_agg[NN0 * D];     // holds MEAN after gather
__device__ float          g_h[NN0 * D];
__device__ float          g_xa[N1 * D];
__device__ float          g_xb[N2 * D];
__device__ float          g_score[NN0];
__device__ int            g_newid[NN0];
__device__ int            g_oldof[N1];
__device__ float          g_vals[N1];
__device__ int            g_src[EDGES];
__device__ int            g_dst[EDGES];
__device__ unsigned char  g_mask[EDGES];
__device__ int            g_ecnt[NN0];
__device__ int            g_eoff[NN0];
__device__ int            g_ecur[NN0];
__device__ int            g_csr[EDGES];
__device__ float          g_s[BG * 256];
__device__ float          g_invnorm3[3];

__device__ __forceinline__ const float* sel_in(const float* ext, int sel) {
    return (sel == 1) ? g_xa : (sel == 2) ? g_xb : ext;
}
__device__ __forceinline__ float* sel_out(int sel) {
    return (sel == 1) ? g_xa : g_xb;
}

// ===================== tf32 mma helpers (sm_80+, no 'a' features) ===========
__device__ __forceinline__ void mma_tf32(float* d,
    uint32_t a0, uint32_t a1, uint32_t a2, uint32_t a3,
    uint32_t b0, uint32_t b1)
{
    asm volatile(
        "mma.sync.aligned.m16n8k8.row.col.f32.tf32.tf32.f32 "
        "{%0,%1,%2,%3}, {%4,%5,%6,%7}, {%8,%9}, {%0,%1,%2,%3};"
        : "+f"(d[0]), "+f"(d[1]), "+f"(d[2]), "+f"(d[3])
        : "r"(a0), "r"(a1), "r"(a2), "r"(a3), "r"(b0), "r"(b1));
}

__device__ __forceinline__ void f32_to_tf32x2(float v, uint32_t& hi, uint32_t& lo) {
    asm("cvt.rna.tf32.f32 %0, %1;" : "=r"(hi) : "f"(v));
    float r = v - __uint_as_float(hi);
    asm("cvt.rna.tf32.f32 %0, %1;" : "=r"(lo) : "f"(r));
}

// ===================== init =================================================
__global__ void init_kernel(const int* __restrict__ ei) {
    int i = blockIdx.x * blockDim.x + threadIdx.x;
    if (i < EDGES) {
        g_src[i] = ei[i];
        g_dst[i] = ei[EDGES + i];
        g_mask[i] = 1;
    }
    if (i < BG * 256) g_s[i] = 0.0f;
}

// ===================== CSR build: zero counts, count, scan, fill ============
__global__ void ecnt_zero_kernel(int n) {
    int i = blockIdx.x * blockDim.x + threadIdx.x;
    if (i < n) g_ecnt[i] = 0;
}

__global__ void ecount_kernel() {
    int e = blockIdx.x * blockDim.x + threadIdx.x;
    if (e >= EDGES) return;
    if (!g_mask[e]) return;
    atomicAdd(&g_ecnt[g_dst[e]], 1);
}

// One block (1024 threads) per graph: exclusive scan of counts within graph.
__global__ __launch_bounds__(1024) void escan_kernel(int Npg) {
    __shared__ int sc[1024];
    int g = blockIdx.x, t = threadIdx.x;
    int node = g * Npg + t;
    int v = (t < Npg) ? g_ecnt[node] : 0;
    sc[t] = v;
    __syncthreads();
    for (int o = 1; o < 1024; o <<= 1) {
        int a = (t >= o) ? sc[t - o] : 0;
        __syncthreads();
        sc[t] += a;
        __syncthreads();
    }
    if (t < Npg) {
        int off = g * EPG + sc[t] - v;   // exclusive
        g_eoff[node] = off;
        g_ecur[node] = off;
    }
}

__global__ void efill_kernel() {
    int e = blockIdx.x * blockDim.x + threadIdx.x;
    if (e >= EDGES) return;
    if (!g_mask[e]) return;
    int pos = atomicAdd(&g_ecur[g_dst[e]], 1);
    g_csr[pos] = g_src[e];
}

// ===================== gather-mean: g_agg[node] = mean_j x[src_j] ===========
__global__ void gather_mean_kernel(const float* __restrict__ x_ext, int xsel, int n) {
    int gid  = blockIdx.x * blockDim.x + threadIdx.x;
    int node = gid >> 5;
    if (node >= n) return;
    int lane = gid & 31;
    const float* x = sel_in(x_ext, xsel);
    int off = g_eoff[node], cnt = g_ecnt[node];

    float4 acc = make_float4(0.f, 0.f, 0.f, 0.f);
    int i = 0;
    for (; i + 4 <= cnt; i += 4) {
        int s0 = g_csr[off + i], s1 = g_csr[off + i + 1];
        int s2 = g_csr[off + i + 2], s3 = g_csr[off + i + 3];
        float4 v0 = ((const float4*)(x + (size_t)s0 * D))[lane];
        float4 v1 = ((const float4*)(x + (size_t)s1 * D))[lane];
        float4 v2 = ((const float4*)(x + (size_t)s2 * D))[lane];
        float4 v3 = ((const float4*)(x + (size_t)s3 * D))[lane];
        acc.x += v0.x + v1.x + v2.x + v3.x;
        acc.y += v0.y + v1.y + v2.y + v3.y;
        acc.z += v0.z + v1.z + v2.z + v3.z;
        acc.w += v0.w + v1.w + v2.w + v3.w;
    }
    for (; i < cnt; i++) {
        int s = g_csr[off + i];
        float4 v = ((const float4*)(x + (size_t)s * D))[lane];
        acc.x += v.x; acc.y += v.y; acc.z += v.z; acc.w += v.w;
    }
    float inv = 1.0f / (float)max(cnt, 1);
    acc.x *= inv; acc.y *= inv; acc.z *= inv; acc.w *= inv;
    ((float4*)(g_agg + (size_t)node * D))[lane] = acc;
}

// ===================== invnorm for all 3 pool weights =======================
__global__ void invnorm_kernel(const float* __restrict__ pw1,
                               const float* __restrict__ pw2,
                               const float* __restrict__ pw3) {
    const float* pw = (blockIdx.x == 0) ? pw1 : (blockIdx.x == 1) ? pw2 : pw3;
    __shared__ float red[128];
    float v = pw[threadIdx.x];
    red[threadIdx.x] = v * v;
    __syncthreads();
    for (int s = 64; s > 0; s >>= 1) {
        if (threadIdx.x < s) red[threadIdx.x] += red[threadIdx.x + s];
        __syncthreads();
    }
    if (threadIdx.x == 0) g_invnorm3[blockIdx.x] = rsqrtf(red[0]);
}

// ===================== fused SAGE GEMM (mma.sync tf32x3) + score ============
#define AS_STRIDE 20
#define BS_STRIDE 136

__device__ __forceinline__ void sage_gload(float4* ra, float4* rb, int s,
    int row0, int n, const float* __restrict__ x,
    const float* __restrict__ Wl, const float* __restrict__ Wr, int tid)
{
    int k0 = s * 16;
#pragma unroll
    for (int p = 0; p < 2; p++) {
        int idx = tid + p * 256;
        int r = idx >> 2, c4 = (idx & 3) << 2;
        int node = row0 + r; if (node >= n) node = n - 1;
        float4 v;
        if (k0 < 128) {
            v = *(const float4*)(g_agg + (size_t)node * D + k0 + c4);
        } else {
            v = *(const float4*)(x + (size_t)node * D + (k0 - 128) + c4);
        }
        ra[p] = v;
        int k = idx >> 5, n4 = (idx & 31) << 2;
        int kg = k0 + k;
        const float* Ws = (kg < 128) ? (Wl + (size_t)kg * D + n4)
                                     : (Wr + (size_t)(kg - 128) * D + n4);
        rb[p] = *(const float4*)Ws;
    }
}

__device__ __forceinline__ void sage_sstore(const float4* ra, const float4* rb,
    float* Ab, float* Bb, int tid)
{
#pragma unroll
    for (int p = 0; p < 2; p++) {
        int idx = tid + p * 256;
        int r = idx >> 2, c4 = (idx & 3) << 2;
        *(float4*)(Ab + r * AS_STRIDE + c4) = ra[p];
        int k = idx >> 5, n4 = (idx & 31) << 2;
        *(float4*)(Bb + k * BS_STRIDE + n4) = rb[p];
    }
}

__device__ __forceinline__ void sage_compute(float acc[2][8][4],
    const float* Ab, const float* Bb, int wm, int wn, int l4, int lq)
{
#pragma unroll
    for (int q = 0; q < 2; q++) {
        int kb = q * 8;
        uint32_t ah[2][4], al[2][4];
#pragma unroll
        for (int i = 0; i < 2; i++) {
            int rbase = wm * 32 + i * 16 + l4;
#pragma unroll
            for (int e = 0; e < 4; e++) {
                int rr = rbase + (e & 1) * 8;
                int kk = kb + lq + (e >> 1) * 4;
                f32_to_tf32x2(Ab[rr * AS_STRIDE + kk], ah[i][e], al[i][e]);
            }
        }
#pragma unroll
        for (int j = 0; j < 8; j++) {
            int nb = wn * 64 + j * 8 + l4;
            uint32_t bh0, blo0, bh1, blo1;
            f32_to_tf32x2(Bb[(kb + lq) * BS_STRIDE + nb], bh0, blo0);
            f32_to_tf32x2(Bb[(kb + lq + 4) * BS_STRIDE + nb], bh1, blo1);
#pragma unroll
            for (int i = 0; i < 2; i++) {
                mma_tf32(acc[i][j], ah[i][0], ah[i][1], ah[i][2], ah[i][3], bh0, bh1);
                mma_tf32(acc[i][j], ah[i][0], ah[i][1], ah[i][2], ah[i][3], blo0, blo1);
                mma_tf32(acc[i][j], al[i][0], al[i][1], al[i][2], al[i][3], bh0, bh1);
            }
        }
    }
}

__global__ __launch_bounds__(256) void sage_mma_kernel(
    const float* __restrict__ x_ext, int xsel,
    const float* __restrict__ Wl, const float* __restrict__ bl,
    const float* __restrict__ Wr, const float* __restrict__ pw,
    int layer, int n)
{
    __shared__ float As[2][128 * AS_STRIDE];
    __shared__ float Bs[2][16 * BS_STRIDE];
    __shared__ float sBias[128], sPw[128];
    __shared__ float sDot[128][2];

    const float* x = sel_in(x_ext, xsel);
    int tid = threadIdx.x;
    int wid = tid >> 5, lane = tid & 31;
    int wm = wid & 3, wn = wid >> 2;
    int l4 = lane >> 2, lq = lane & 3;
    int row0 = blockIdx.x * 128;

    if (tid < 128) {
        sBias[tid] = bl[tid];
        sPw[tid]   = pw[tid];
    }
    __syncthreads();

    float acc[2][8][4];
#pragma unroll
    for (int i = 0; i < 2; i++)
#pragma unroll
        for (int j = 0; j < 8; j++)
#pragma unroll
            for (int e = 0; e < 4; e++) acc[i][j][e] = 0.0f;

    float4 ra[2], rb[2];
    sage_gload(ra, rb, 0, row0, n, x, Wl, Wr, tid);
    sage_sstore(ra, rb, As[0], Bs[0], tid);
    __syncthreads();

#pragma unroll 1
    for (int s = 0; s < 16; s++) {
        if (s < 15) sage_gload(ra, rb, s + 1, row0, n, x, Wl, Wr, tid);
        sage_compute(acc, As[s & 1], Bs[s & 1], wm, wn, l4, lq);
        if (s < 15) {
            sage_sstore(ra, rb, As[(s + 1) & 1], Bs[(s + 1) & 1], tid);
            __syncthreads();
        }
    }

    // ---- epilogue: bias + relu + store h + fused pool-score dot ----
    float dA[2] = {0.0f, 0.0f}, dB[2] = {0.0f, 0.0f};
#pragma unroll
    for (int i = 0; i < 2; i++) {
        int rA = wm * 32 + i * 16 + l4;
        int nodeA = row0 + rA, nodeB = nodeA + 8;
#pragma unroll
        for (int j = 0; j < 8; j++) {
            int c0 = wn * 64 + j * 8 + 2 * lq;
            float o0 = fmaxf(acc[i][j][0] + sBias[c0],     0.0f);
            float o1 = fmaxf(acc[i][j][1] + sBias[c0 + 1], 0.0f);
            float o2 = fmaxf(acc[i][j][2] + sBias[c0],     0.0f);
            float o3 = fmaxf(acc[i][j][3] + sBias[c0 + 1], 0.0f);
            if (nodeA < n) *(float2*)(g_h + (size_t)nodeA * D + c0) = make_float2(o0, o1);
            if (nodeB < n) *(float2*)(g_h + (size_t)nodeB * D + c0) = make_float2(o2, o3);
            dA[i] += o0 * sPw[c0] + o1 * sPw[c0 + 1];
            dB[i] += o2 * sPw[c0] + o3 * sPw[c0 + 1];
        }
    }
#pragma unroll
    for (int o = 1; o <= 2; o <<= 1) {
        dA[0] += __shfl_xor_sync(0xffffffffu, dA[0], o);
        dA[1] += __shfl_xor_sync(0xffffffffu, dA[1], o);
        dB[0] += __shfl_xor_sync(0xffffffffu, dB[0], o);
        dB[1] += __shfl_xor_sync(0xffffffffu, dB[1], o);
    }
    if (lq == 0) {
        sDot[wm * 32 + l4][wn]      = dA[0];
        sDot[wm * 32 + l4 + 8][wn]  = dB[0];
        sDot[wm * 32 + l4 + 16][wn] = dA[1];
        sDot[wm * 32 + l4 + 24][wn] = dB[1];
    }
    __syncthreads();
    if (tid < 128 && row0 + tid < n) {
        float dsum = sDot[tid][0] + sDot[tid][1];
        g_score[row0 + tid] = tanhf(dsum * g_invnorm3[layer]);
    }
}

// ===================== topk / gather / readout / remap / mlp ================
__global__ void topk_kernel(int Npg, int K) {
    __shared__ float ss[1024];
    __shared__ int   si[1024];
    int g = blockIdx.x, t = threadIdx.x;
    if (t < Npg) { ss[t] = g_score[g * Npg + t]; si[t] = t; }
    else         { ss[t] = -1e30f;               si[t] = -1; }
    __syncthreads();
    for (int k = 2; k <= 1024; k <<= 1) {
        for (int j = k >> 1; j > 0; j >>= 1) {
            int ixj = t ^ j;
            if (ixj > t) {
                bool desc = ((t & k) == 0);
                float a = ss[t], b = ss[ixj];
                bool sw = desc ? (a < b) : (a > b);
                if (sw) {
                    ss[t] = b; ss[ixj] = a;
                    int tmp = si[t]; si[t] = si[ixj]; si[ixj] = tmp;
                }
            }
            __syncthreads();
        }
    }
    if (t < Npg) {
        int oldg = g * Npg + si[t];
        if (t < K) {
            int nw = g * K + t;
            g_newid[oldg] = nw;
            g_oldof[nw]   = oldg;
            g_vals[nw]    = ss[t];
        } else {
            g_newid[oldg] = -1;
        }
    }
}

__global__ void pool_gather_kernel(int outsel) {
    float* xout = sel_out(outsel);
    int nw = blockIdx.x, t = threadIdx.x;   // 32 threads
    int old = g_oldof[nw];
    float v  = g_vals[nw];
    float4 h4 = ((const float4*)(g_h + (size_t)old * D))[t];
    float4 o = make_float4(h4.x * v, h4.y * v, h4.z * v, h4.w * v);
    ((float4*)(xout + (size_t)nw * D))[t] = o;
}

__global__ void readout_kernel(int insel, int K) {
    __shared__ float smax[4][128];
    __shared__ float ssum[4][128];
    const float* xn = sel_in(nullptr, insel);
    int g = blockIdx.x, t = threadIdx.x;
    int c = t >> 7, f = t & 127;
    float mx = -1e30f, sm = 0.0f;
    for (int k = c; k < K; k += 4) {
        float v = xn[((size_t)(g * K + k)) * D + f];
        mx = fmaxf(mx, v);
        sm += v;
    }
    smax[c][f] = mx; ssum[c][f] = sm;
    __syncthreads();
    if (c == 0) {
#pragma unroll
        for (int i = 1; i < 4; i++) { mx = fmaxf(mx, smax[i][f]); sm += ssum[i][f]; }
        g_s[g * 256 + f]       += mx;
        g_s[g * 256 + 128 + f] += sm / (float)K;
    }
}

__global__ void remap_kernel() {
    int e = blockIdx.x * blockDim.x + threadIdx.x;
    if (e >= EDGES) return;
    if (!g_mask[e]) return;
    int s = g_newid[g_src[e]];
    int d = g_newid[g_dst[e]];
    if (s < 0 || d < 0) { g_mask[e] = 0; g_src[e] = 0; g_dst[e] = 0; }
    else                { g_src[e] = s; g_dst[e] = d; }
}

__global__ void mlp_kernel(const float* __restrict__ W1, const float* __restrict__ b1,
                           const float* __restrict__ W2, const float* __restrict__ b2,
                           const float* __restrict__ W3, const float* __restrict__ b3,
                           float* __restrict__ out)
{
    __shared__ float ss[256];
    __shared__ float h1[128];
    __shared__ float h2[64];
    int g = blockIdx.x, t = threadIdx.x;   // 128 threads
    ss[t]       = g_s[g * 256 + t];
    ss[t + 128] = g_s[g * 256 + 128 + t];
    __syncthreads();
    float a = b1[t];
    for (int k = 0; k < 256; k++) a += ss[k] * W1[k * 128 + t];
    h1[t] = fmaxf(a, 0.0f);
    __syncthreads();
    if (t < 64) {
        float a2 = b2[t];
        for (int k = 0; k < 128; k++) a2 += h1[k] * W2[k * 64 + t];
        h2[t] = fmaxf(a2, 0.0f);
    }
    __syncthreads();
    if (t == 0) {
        float s2 = 0.0f;
        for (int i = 0; i < 64; i++) s2 += h2[i] * W3[i];
        out[g] = 1.0f / (1.0f + expf(-(s2 + b3[0])));
    }
}

// ===================== host orchestration ===================================
static void run_layer(const float* x_ext, int xsel, int n, int Npg, int K,
                      const float* Wl, const float* bl, const float* Wr,
                      const float* pw, int layer, int outsel, bool remap)
{
    ecnt_zero_kernel<<<(n + 255) / 256, 256>>>(n);
    ecount_kernel<<<(EDGES + 255) / 256, 256>>>();
    escan_kernel<<<BG, 1024>>>(Npg);
    efill_kernel<<<(EDGES + 255) / 256, 256>>>();
    gather_mean_kernel<<<(n * 32 + 255) / 256, 256>>>(x_ext, xsel, n);
    sage_mma_kernel<<<(n + 127) / 128, 256>>>(x_ext, xsel, Wl, bl, Wr, pw, layer, n);
    topk_kernel<<<BG, 1024>>>(Npg, K);
    pool_gather_kernel<<<BG * K, 32>>>(outsel);
    readout_kernel<<<BG, 512>>>(outsel, K);
    if (remap) remap_kernel<<<(EDGES + 255) / 256, 256>>>();
}

extern "C" void kernel_launch(void* const* d_in, const int* in_sizes, int n_in,
                              void* d_out, int out_size)
{
    const float* x   = (const float*)d_in[0];
    const int*   ei  = (const int*)  d_in[1];
    const float* Wl1 = (const float*)d_in[2];
    const float* bl1 = (const float*)d_in[3];
    const float* Wr1 = (const float*)d_in[4];
    const float* pw1 = (const float*)d_in[5];
    const float* Wl2 = (const float*)d_in[6];
    const float* bl2 = (const float*)d_in[7];
    const float* Wr2 = (const float*)d_in[8];
    const float* pw2 = (const float*)d_in[9];
    const float* Wl3 = (const float*)d_in[10];
    const float* bl3 = (const float*)d_in[11];
    const float* Wr3 = (const float*)d_in[12];
    const float* pw3 = (const float*)d_in[13];
    const float* W1  = (const float*)d_in[14];
    const float* b1  = (const float*)d_in[15];
    const float* W2  = (const float*)d_in[16];
    const float* b2  = (const float*)d_in[17];
    const float* W3  = (const float*)d_in[18];
    const float* b3  = (const float*)d_in[19];

    init_kernel<<<EDGES / 256, 256>>>(ei);
    invnorm_kernel<<<3, 128>>>(pw1, pw2, pw3);

    run_layer(x,       0, NN0, NPG0, K1, Wl1, bl1, Wr1, pw1, 0, 1, true);
    run_layer(nullptr, 1, N1,  K1,   K2, Wl2, bl2, Wr2, pw2, 1, 2, true);
    run_layer(nullptr, 2, N2,  K2,   K3, Wl3, bl3, Wr3, pw3, 2, 1, false);

    mlp_kernel<<<BG, 128>>>(W1, b1, W2, b2, W3, b3, (float*)d_out);
}

// round 9
// speedup vs baseline: 2.3505x; 1.0868x over previous
#include <cuda_runtime.h>
#include <cstdint>
#include <math.h>

// Problem constants (fixed by setup_inputs: B=64, N=1024, DEG=16, D=128)
#define D       128
#define BG      64
#define NPG0    1024
#define NN0     (BG * NPG0)        // 65536 nodes layer 1
#define EDGES   (BG * NPG0 * 16)   // 1048576 edges
#define EPG     16384              // CSR capacity per graph
#define K1      820
#define K2      656
#define K3      525
#define N1      (BG * K1)          // 52480
#define N2      (BG * K2)          // 41984
#define N3      (BG * K3)          // 33600

// ---------------- scratch (device globals; no allocation allowed) -----------
__device__ float          g_agg[NN0 * D];     // holds MEAN after gather
__device__ float          g_h[NN0 * D];
__device__ float          g_xa[N1 * D];
__device__ float          g_xb[N2 * D];
__device__ float          g_score[NN0];
__device__ int            g_newid[NN0];
__device__ int            g_oldof[N1];
__device__ float          g_vals[N1];
__device__ int            g_src[EDGES];
__device__ int            g_dst[EDGES];
__device__ unsigned char  g_mask[EDGES];
__device__ int            g_ecnt[NN0];
__device__ int            g_eoff[NN0];
__device__ int            g_ecur[NN0];
__device__ int            g_csr[EDGES];
__device__ float          g_s[BG * 256];
__device__ float          g_invnorm3[3];
__device__ float          g_Bhi[256 * 128];   // tf32-hi of [Wl;Wr]
__device__ float          g_Blo[256 * 128];   // tf32-lo of [Wl;Wr]

__device__ __forceinline__ const float* sel_in(const float* ext, int sel) {
    return (sel == 1) ? g_xa : (sel == 2) ? g_xb : ext;
}
__device__ __forceinline__ float* sel_out(int sel) {
    return (sel == 1) ? g_xa : g_xb;
}

// ===================== tf32 mma helpers (sm_80+, no 'a' features) ===========
__device__ __forceinline__ void mma_tf32(float* d,
    uint32_t a0, uint32_t a1, uint32_t a2, uint32_t a3,
    uint32_t b0, uint32_t b1)
{
    asm volatile(
        "mma.sync.aligned.m16n8k8.row.col.f32.tf32.tf32.f32 "
        "{%0,%1,%2,%3}, {%4,%5,%6,%7}, {%8,%9}, {%0,%1,%2,%3};"
        : "+f"(d[0]), "+f"(d[1]), "+f"(d[2]), "+f"(d[3])
        : "r"(a0), "r"(a1), "r"(a2), "r"(a3), "r"(b0), "r"(b1));
}

__device__ __forceinline__ void f32_to_tf32x2(float v, uint32_t& hi, uint32_t& lo) {
    asm("cvt.rna.tf32.f32 %0, %1;" : "=r"(hi) : "f"(v));
    float r = v - __uint_as_float(hi);
    asm("cvt.rna.tf32.f32 %0, %1;" : "=r"(lo) : "f"(r));
}

// ===================== init =================================================
__global__ void init_kernel(const int* __restrict__ ei) {
    int i = blockIdx.x * blockDim.x + threadIdx.x;
    if (i < EDGES) {
        g_src[i] = ei[i];
        g_dst[i] = ei[EDGES + i];
        g_mask[i] = 1;
    }
    if (i < BG * 256) g_s[i] = 0.0f;
}

// ===================== per-layer weight split (runs once per layer) =========
__global__ void split_w_kernel(const float* __restrict__ Wl,
                               const float* __restrict__ Wr) {
    int i = blockIdx.x * blockDim.x + threadIdx.x;
    if (i >= 256 * 128) return;
    int kg = i >> 7, n = i & 127;
    float v = (kg < 128) ? Wl[(size_t)kg * 128 + n] : Wr[(size_t)(kg - 128) * 128 + n];
    uint32_t hi, lo; f32_to_tf32x2(v, hi, lo);
    g_Bhi[i] = __uint_as_float(hi);
    g_Blo[i] = __uint_as_float(lo);
}

// ===================== CSR build: zero counts, count, scan, fill ============
__global__ void ecnt_zero_kernel(int n) {
    int i = blockIdx.x * blockDim.x + threadIdx.x;
    if (i < n) g_ecnt[i] = 0;
}

__global__ void ecount_kernel() {
    int e = blockIdx.x * blockDim.x + threadIdx.x;
    if (e >= EDGES) return;
    if (!g_mask[e]) return;
    atomicAdd(&g_ecnt[g_dst[e]], 1);
}

__global__ __launch_bounds__(1024) void escan_kernel(int Npg) {
    __shared__ int sc[1024];
    int g = blockIdx.x, t = threadIdx.x;
    int node = g * Npg + t;
    int v = (t < Npg) ? g_ecnt[node] : 0;
    sc[t] = v;
    __syncthreads();
    for (int o = 1; o < 1024; o <<= 1) {
        int a = (t >= o) ? sc[t - o] : 0;
        __syncthreads();
        sc[t] += a;
        __syncthreads();
    }
    if (t < Npg) {
        int off = g * EPG + sc[t] - v;   // exclusive
        g_eoff[node] = off;
        g_ecur[node] = off;
    }
}

__global__ void efill_kernel() {
    int e = blockIdx.x * blockDim.x + threadIdx.x;
    if (e >= EDGES) return;
    if (!g_mask[e]) return;
    int pos = atomicAdd(&g_ecur[g_dst[e]], 1);
    g_csr[pos] = g_src[e];
}

// ===================== gather-mean: g_agg[node] = mean_j x[src_j] ===========
__global__ void gather_mean_kernel(const float* __restrict__ x_ext, int xsel, int n) {
    int gid  = blockIdx.x * blockDim.x + threadIdx.x;
    int node = gid >> 5;
    if (node >= n) return;
    int lane = gid & 31;
    const float* x = sel_in(x_ext, xsel);
    int off = g_eoff[node], cnt = g_ecnt[node];

    float4 acc = make_float4(0.f, 0.f, 0.f, 0.f);
    int i = 0;
    for (; i + 4 <= cnt; i += 4) {
        int s0 = g_csr[off + i], s1 = g_csr[off + i + 1];
        int s2 = g_csr[off + i + 2], s3 = g_csr[off + i + 3];
        float4 v0 = ((const float4*)(x + (size_t)s0 * D))[lane];
        float4 v1 = ((const float4*)(x + (size_t)s1 * D))[lane];
        float4 v2 = ((const float4*)(x + (size_t)s2 * D))[lane];
        float4 v3 = ((const float4*)(x + (size_t)s3 * D))[lane];
        acc.x += v0.x + v1.x + v2.x + v3.x;
        acc.y += v0.y + v1.y + v2.y + v3.y;
        acc.z += v0.z + v1.z + v2.z + v3.z;
        acc.w += v0.w + v1.w + v2.w + v3.w;
    }
    for (; i < cnt; i++) {
        int s = g_csr[off + i];
        float4 v = ((const float4*)(x + (size_t)s * D))[lane];
        acc.x += v.x; acc.y += v.y; acc.z += v.z; acc.w += v.w;
    }
    float inv = 1.0f / (float)max(cnt, 1);
    acc.x *= inv; acc.y *= inv; acc.z *= inv; acc.w *= inv;
    ((float4*)(g_agg + (size_t)node * D))[lane] = acc;
}

// ===================== invnorm for all 3 pool weights =======================
__global__ void invnorm_kernel(const float* __restrict__ pw1,
                               const float* __restrict__ pw2,
                               const float* __restrict__ pw3) {
    const float* pw = (blockIdx.x == 0) ? pw1 : (blockIdx.x == 1) ? pw2 : pw3;
    __shared__ float red[128];
    float v = pw[threadIdx.x];
    red[threadIdx.x] = v * v;
    __syncthreads();
    for (int s = 64; s > 0; s >>= 1) {
        if (threadIdx.x < s) red[threadIdx.x] += red[threadIdx.x + s];
        __syncthreads();
    }
    if (threadIdx.x == 0) g_invnorm3[blockIdx.x] = rsqrtf(red[0]);
}

// ===================== fused SAGE GEMM (mma.sync tf32x3) + score ============
#define AS_STRIDE 20
#define BS_STRIDE 136
#define AS_WORDS  (128 * AS_STRIDE)
#define BS_WORDS  (16 * BS_STRIDE)
#define DYN_BYTES ((2 * AS_WORDS + 4 * BS_WORDS) * 4)

__device__ __forceinline__ void sage_gload(float4* ra, float4* rbh, float4* rbl,
    int s, int row0, int n, const float* __restrict__ x, int tid)
{
    int k0 = s * 16;
#pragma unroll
    for (int p = 0; p < 2; p++) {
        int idx = tid + p * 256;
        int r = idx >> 2, c4 = (idx & 3) << 2;
        int node = row0 + r; if (node >= n) node = n - 1;
        float4 v;
        if (k0 < 128) {
            v = *(const float4*)(g_agg + (size_t)node * D + k0 + c4);
        } else {
            v = *(const float4*)(x + (size_t)node * D + (k0 - 128) + c4);
        }
        ra[p] = v;
        int k = idx >> 5, n4 = (idx & 31) << 2;
        size_t woff = (size_t)(k0 + k) * 128 + n4;
        rbh[p] = *(const float4*)(g_Bhi + woff);
        rbl[p] = *(const float4*)(g_Blo + woff);
    }
}

__device__ __forceinline__ void sage_sstore(const float4* ra, const float4* rbh,
    const float4* rbl, float* Ab, float* Bh, float* Bl, int tid)
{
#pragma unroll
    for (int p = 0; p < 2; p++) {
        int idx = tid + p * 256;
        int r = idx >> 2, c4 = (idx & 3) << 2;
        *(float4*)(Ab + r * AS_STRIDE + c4) = ra[p];
        int k = idx >> 5, n4 = (idx & 31) << 2;
        *(float4*)(Bh + k * BS_STRIDE + n4) = rbh[p];
        *(float4*)(Bl + k * BS_STRIDE + n4) = rbl[p];
    }
}

__device__ __forceinline__ void sage_compute(float acc[2][8][4],
    const float* Ab, const float* Bh, const float* Bl,
    int wm, int wn, int l4, int lq)
{
#pragma unroll
    for (int q = 0; q < 2; q++) {
        int kb = q * 8;
        uint32_t ah[2][4], al[2][4];
#pragma unroll
        for (int i = 0; i < 2; i++) {
            int rbase = wm * 32 + i * 16 + l4;
#pragma unroll
            for (int e = 0; e < 4; e++) {
                int rr = rbase + (e & 1) * 8;
                int kk = kb + lq + (e >> 1) * 4;
                f32_to_tf32x2(Ab[rr * AS_STRIDE + kk], ah[i][e], al[i][e]);
            }
        }
#pragma unroll
        for (int j = 0; j < 8; j++) {
            int nb = wn * 64 + j * 8 + l4;
            uint32_t bh0 = __float_as_uint(Bh[(kb + lq) * BS_STRIDE + nb]);
            uint32_t bh1 = __float_as_uint(Bh[(kb + lq + 4) * BS_STRIDE + nb]);
            uint32_t bl0 = __float_as_uint(Bl[(kb + lq) * BS_STRIDE + nb]);
            uint32_t bl1 = __float_as_uint(Bl[(kb + lq + 4) * BS_STRIDE + nb]);
#pragma unroll
            for (int i = 0; i < 2; i++) {
                mma_tf32(acc[i][j], ah[i][0], ah[i][1], ah[i][2], ah[i][3], bh0, bh1);
                mma_tf32(acc[i][j], ah[i][0], ah[i][1], ah[i][2], ah[i][3], bl0, bl1);
                mma_tf32(acc[i][j], al[i][0], al[i][1], al[i][2], al[i][3], bh0, bh1);
            }
        }
    }
}

__global__ __launch_bounds__(256) void sage_mma_kernel(
    const float* __restrict__ x_ext, int xsel,
    const float* __restrict__ bl, const float* __restrict__ pw,
    int layer, int n)
{
    extern __shared__ float dyn[];
    float* As = dyn;                              // 2 x 128 x AS_STRIDE
    float* Bh = dyn + 2 * AS_WORDS;               // 2 x 16 x BS_STRIDE
    float* Bl = Bh + 2 * BS_WORDS;                // 2 x 16 x BS_STRIDE
    __shared__ float sBias[128], sPw[128];
    __shared__ float sDot[128][2];

    const float* x = sel_in(x_ext, xsel);
    int tid = threadIdx.x;
    int wid = tid >> 5, lane = tid & 31;
    int wm = wid & 3, wn = wid >> 2;
    int l4 = lane >> 2, lq = lane & 3;
    int row0 = blockIdx.x * 128;

    if (tid < 128) {
        sBias[tid] = bl[tid];
        sPw[tid]   = pw[tid];
    }
    __syncthreads();

    float acc[2][8][4];
#pragma unroll
    for (int i = 0; i < 2; i++)
#pragma unroll
        for (int j = 0; j < 8; j++)
#pragma unroll
            for (int e = 0; e < 4; e++) acc[i][j][e] = 0.0f;

    float4 ra[2], rbh[2], rbl[2];
    sage_gload(ra, rbh, rbl, 0, row0, n, x, tid);
    sage_sstore(ra, rbh, rbl, As, Bh, Bl, tid);
    __syncthreads();

#pragma unroll 1
    for (int s = 0; s < 16; s++) {
        int cur = s & 1, nxt = cur ^ 1;
        if (s < 15) sage_gload(ra, rbh, rbl, s + 1, row0, n, x, tid);
        sage_compute(acc, As + cur * AS_WORDS, Bh + cur * BS_WORDS,
                     Bl + cur * BS_WORDS, wm, wn, l4, lq);
        if (s < 15) {
            sage_sstore(ra, rbh, rbl, As + nxt * AS_WORDS,
                        Bh + nxt * BS_WORDS, Bl + nxt * BS_WORDS, tid);
            __syncthreads();
        }
    }

    // ---- epilogue: bias + relu + store h + fused pool-score dot ----
    float dA[2] = {0.0f, 0.0f}, dB[2] = {0.0f, 0.0f};
#pragma unroll
    for (int i = 0; i < 2; i++) {
        int rA = wm * 32 + i * 16 + l4;
        int nodeA = row0 + rA, nodeB = nodeA + 8;
#pragma unroll
        for (int j = 0; j < 8; j++) {
            int c0 = wn * 64 + j * 8 + 2 * lq;
            float o0 = fmaxf(acc[i][j][0] + sBias[c0],     0.0f);
            float o1 = fmaxf(acc[i][j][1] + sBias[c0 + 1], 0.0f);
            float o2 = fmaxf(acc[i][j][2] + sBias[c0],     0.0f);
            float o3 = fmaxf(acc[i][j][3] + sBias[c0 + 1], 0.0f);
            if (nodeA < n) *(float2*)(g_h + (size_t)nodeA * D + c0) = make_float2(o0, o1);
            if (nodeB < n) *(float2*)(g_h + (size_t)nodeB * D + c0) = make_float2(o2, o3);
            dA[i] += o0 * sPw[c0] + o1 * sPw[c0 + 1];
            dB[i] += o2 * sPw[c0] + o3 * sPw[c0 + 1];
        }
    }
#pragma unroll
    for (int o = 1; o <= 2; o <<= 1) {
        dA[0] += __shfl_xor_sync(0xffffffffu, dA[0], o);
        dA[1] += __shfl_xor_sync(0xffffffffu, dA[1], o);
        dB[0] += __shfl_xor_sync(0xffffffffu, dB[0], o);
        dB[1] += __shfl_xor_sync(0xffffffffu, dB[1], o);
    }
    if (lq == 0) {
        sDot[wm * 32 + l4][wn]      = dA[0];
        sDot[wm * 32 + l4 + 8][wn]  = dB[0];
        sDot[wm * 32 + l4 + 16][wn] = dA[1];
        sDot[wm * 32 + l4 + 24][wn] = dB[1];
    }
    __syncthreads();
    if (tid < 128 && row0 + tid < n) {
        float dsum = sDot[tid][0] + sDot[tid][1];
        g_score[row0 + tid] = tanhf(dsum * g_invnorm3[layer]);
    }
}

// ===================== topk: register bitonic + shfl ========================
__global__ __launch_bounds__(1024) void topk_kernel(int Npg, int K) {
    __shared__ float ss[1024];
    __shared__ int   si[1024];
    int g = blockIdx.x, t = threadIdx.x;
    float v = (t < Npg) ? g_score[g * Npg + t] : -1e30f;
    int  id = (t < Npg) ? t : -1;

#pragma unroll 1
    for (int k = 2; k <= 1024; k <<= 1) {
        bool desc = ((t & k) == 0);
#pragma unroll 1
        for (int j = k >> 1; j >= 32; j >>= 1) {
            ss[t] = v; si[t] = id;
            __syncthreads();
            float ov = ss[t ^ j]; int oid = si[t ^ j];
            bool keep_max = (desc == ((t & j) == 0));
            bool take = keep_max ? (ov > v) : (ov < v);
            if (take) { v = ov; id = oid; }
            __syncthreads();
        }
        int j0 = (k >> 1 < 16) ? (k >> 1) : 16;
#pragma unroll 1
        for (int j = j0; j >= 1; j >>= 1) {
            float ov = __shfl_xor_sync(0xffffffffu, v, j);
            int  oid = __shfl_xor_sync(0xffffffffu, id, j);
            bool keep_max = (desc == ((t & j) == 0));
            bool take = keep_max ? (ov > v) : (ov < v);
            if (take) { v = ov; id = oid; }
        }
    }
    // thread t holds rank-t element (descending), id = original in-graph index
    if (t < Npg) {
        int oldg = g * Npg + id;
        if (t < K) {
            int nw = g * K + t;
            g_newid[oldg] = nw;
            g_oldof[nw]   = oldg;
            g_vals[nw]    = v;
        } else {
            g_newid[oldg] = -1;
        }
    }
}

// ===================== pool gather / readout / remap / mlp ==================
__global__ void pool_gather_kernel(int outsel) {
    float* xout = sel_out(outsel);
    int nw = blockIdx.x, t = threadIdx.x;   // 32 threads
    int old = g_oldof[nw];
    float v  = g_vals[nw];
    float4 h4 = ((const float4*)(g_h + (size_t)old * D))[t];
    float4 o = make_float4(h4.x * v, h4.y * v, h4.z * v, h4.w * v);
    ((float4*)(xout + (size_t)nw * D))[t] = o;
}

__global__ void readout_kernel(int insel, int K) {
    __shared__ float smax[4][128];
    __shared__ float ssum[4][128];
    const float* xn = sel_in(nullptr, insel);
    int g = blockIdx.x, t = threadIdx.x;
    int c = t >> 7, f = t & 127;
    float mx = -1e30f, sm = 0.0f;
    for (int k = c; k < K; k += 4) {
        float v = xn[((size_t)(g * K + k)) * D + f];
        mx = fmaxf(mx, v);
        sm += v;
    }
    smax[c][f] = mx; ssum[c][f] = sm;
    __syncthreads();
    if (c == 0) {
#pragma unroll
        for (int i = 1; i < 4; i++) { mx = fmaxf(mx, smax[i][f]); sm += ssum[i][f]; }
        g_s[g * 256 + f]       += mx;
        g_s[g * 256 + 128 + f] += sm / (float)K;
    }
}

__global__ void remap_kernel() {
    int e = blockIdx.x * blockDim.x + threadIdx.x;
    if (e >= EDGES) return;
    if (!g_mask[e]) return;
    int s = g_newid[g_src[e]];
    int d = g_newid[g_dst[e]];
    if (s < 0 || d < 0) { g_mask[e] = 0; g_src[e] = 0; g_dst[e] = 0; }
    else                { g_src[e] = s; g_dst[e] = d; }
}

__global__ void mlp_kernel(const float* __restrict__ W1, const float* __restrict__ b1,
                           const float* __restrict__ W2, const float* __restrict__ b2,
                           const float* __restrict__ W3, const float* __restrict__ b3,
                           float* __restrict__ out)
{
    __shared__ float ss[256];
    __shared__ float h1[128];
    __shared__ float h2[64];
    int g = blockIdx.x, t = threadIdx.x;   // 128 threads
    ss[t]       = g_s[g * 256 + t];
    ss[t + 128] = g_s[g * 256 + 128 + t];
    __syncthreads();
    float a = b1[t];
    for (int k = 0; k < 256; k++) a += ss[k] * W1[k * 128 + t];
    h1[t] = fmaxf(a, 0.0f);
    __syncthreads();
    if (t < 64) {
        float a2 = b2[t];
        for (int k = 0; k < 128; k++) a2 += h1[k] * W2[k * 64 + t];
        h2[t] = fmaxf(a2, 0.0f);
    }
    __syncthreads();
    if (t == 0) {
        float s2 = 0.0f;
        for (int i = 0; i < 64; i++) s2 += h2[i] * W3[i];
        out[g] = 1.0f / (1.0f + expf(-(s2 + b3[0])));
    }
}

// ===================== host orchestration ===================================
static void run_layer(const float* x_ext, int xsel, int n, int Npg, int K,
                      const float* Wl, const float* bl, const float* Wr,
                      const float* pw, int layer, int outsel, bool remap)
{
    split_w_kernel<<<128, 256>>>(Wl, Wr);
    ecnt_zero_kernel<<<(n + 255) / 256, 256>>>(n);
    ecount_kernel<<<(EDGES + 255) / 256, 256>>>();
    escan_kernel<<<BG, 1024>>>(Npg);
    efill_kernel<<<(EDGES + 255) / 256, 256>>>();
    gather_mean_kernel<<<(n * 32 + 255) / 256, 256>>>(x_ext, xsel, n);
    sage_mma_kernel<<<(n + 127) / 128, 256, DYN_BYTES>>>(x_ext, xsel, bl, pw, layer, n);
    topk_kernel<<<BG, 1024>>>(Npg, K);
    pool_gather_kernel<<<BG * K, 32>>>(outsel);
    readout_kernel<<<BG, 512>>>(outsel, K);
    if (remap) remap_kernel<<<(EDGES + 255) / 256, 256>>>();
}

extern "C" void kernel_launch(void* const* d_in, const int* in_sizes, int n_in,
                              void* d_out, int out_size)
{
    const float* x   = (const float*)d_in[0];
    const int*   ei  = (const int*)  d_in[1];
    const float* Wl1 = (const float*)d_in[2];
    const float* bl1 = (const float*)d_in[3];
    const float* Wr1 = (const float*)d_in[4];
    const float* pw1 = (const float*)d_in[5];
    const float* Wl2 = (const float*)d_in[6];
    const float* bl2 = (const float*)d_in[7];
    const float* Wr2 = (const float*)d_in[8];
    const float* pw2 = (const float*)d_in[9];
    const float* Wl3 = (const float*)d_in[10];
    const float* bl3 = (const float*)d_in[11];
    const float* Wr3 = (const float*)d_in[12];
    const float* pw3 = (const float*)d_in[13];
    const float* W1  = (const float*)d_in[14];
    const float* b1  = (const float*)d_in[15];
    const float* W2  = (const float*)d_in[16];
    const float* b2  = (const float*)d_in[17];
    const float* W3  = (const float*)d_in[18];
    const float* b3  = (const float*)d_in[19];

    cudaFuncSetAttribute(sage_mma_kernel,
                         cudaFuncAttributeMaxDynamicSharedMemorySize, DYN_BYTES);

    init_kernel<<<EDGES / 256, 256>>>(ei);
    invnorm_kernel<<<3, 128>>>(pw1, pw2, pw3);

    run_layer(x,       0, NN0, NPG0, K1, Wl1, bl1, Wr1, pw1, 0, 1, true);
    run_layer(nullptr, 1, N1,  K1,   K2, Wl2, bl2, Wr2, pw2, 1, 2, true);
    run_layer(nullptr, 2, N2,  K2,   K3, Wl3, bl3, Wr3, pw3, 2, 1, false);

    mlp_kernel<<<BG, 128>>>(W1, b1, W2, b2, W3, b3, (float*)d_out);
}